// round 1
// baseline (speedup 1.0000x reference)
#include <cuda_runtime.h>
#include <stdint.h>
#include <math.h>

// Problem dims (fixed by the reference)
#define B_DIM 8192
#define IN_DIM 2048
#define H_DIM 2048

// Output layout: tuple flattened in order
// (new_h, concat_input, pre_gate_i, gate_i, values_i, pre_h)
#define OFF_NEWH    0
#define OFF_CONCAT  (B_DIM * H_DIM)                              // 16777216
#define OFF_PREGATE (OFF_CONCAT + B_DIM * (IN_DIM + H_DIM))      // 50331648
#define OFF_GATE    (OFF_PREGATE + B_DIM * H_DIM)                // 67108864
#define OFF_VALUES  (OFF_GATE + B_DIM * H_DIM)                   // 83886080
#define OFF_PREH    (OFF_VALUES + B_DIM * H_DIM)                 // 100663296

// GEMM tiling
#define BM 128
#define BN 128
#define BK 16
#define KSTRIDE (BK + 4)   // pad to 20 floats -> conflict-free frag loads

__device__ __forceinline__ uint32_t f2tf32(float f) {
    uint32_t r;
    asm("cvt.rna.tf32.f32 %0, %1;" : "=r"(r) : "f"(f));
    return r;
}

__device__ __forceinline__ void store_tf32_v4(float* dst, float4 v) {
    float4 o;
    o.x = __uint_as_float(f2tf32(v.x));
    o.y = __uint_as_float(f2tf32(v.y));
    o.z = __uint_as_float(f2tf32(v.z));
    o.w = __uint_as_float(f2tf32(v.w));
    *(float4*)dst = o;
}

__device__ __forceinline__ float clip01(float x) {
    return fminf(fmaxf(x, 0.0f), 1.0f);
}

__device__ __forceinline__ void mma_tf32(float* c, const uint32_t* a, uint32_t b0, uint32_t b1) {
    asm volatile(
        "mma.sync.aligned.m16n8k8.row.col.f32.tf32.tf32.f32 "
        "{%0,%1,%2,%3}, {%4,%5,%6,%7}, {%8,%9}, {%0,%1,%2,%3};"
        : "+f"(c[0]), "+f"(c[1]), "+f"(c[2]), "+f"(c[3])
        : "r"(a[0]), "r"(a[1]), "r"(a[2]), "r"(a[3]), "r"(b0), "r"(b1));
}

// ---------------------------------------------------------------------------
// Kernel 1: concat_input = [input | state], written as float4 copies
// ---------------------------------------------------------------------------
__global__ void concat_kernel(const float* __restrict__ input,
                              const float* __restrict__ state,
                              float* __restrict__ out) {
    int idx = blockIdx.x * 256 + threadIdx.x;      // float4 index, total 8192*1024
    const float4* inF4 = (const float4*)input;
    const float4* stF4 = (const float4*)state;
    float4* o = (float4*)(out + OFF_CONCAT);
    int b  = idx >> 10;         // row (4096 floats = 1024 f4 per row)
    int c4 = idx & 1023;
    o[idx] = (c4 < 512) ? inF4[b * 512 + c4] : stF4[b * 512 + c4 - 512];
}

// ---------------------------------------------------------------------------
// Kernel 2: pre_gate = concat @ gate_w^T + bias ; gate = clip01(pre_gate)
//   A rows come straight from input/state (no dependence on concat output).
// ---------------------------------------------------------------------------
__global__ __launch_bounds__(256, 2)
void gemm_gate_kernel(const float* __restrict__ input,
                      const float* __restrict__ state,
                      const float* __restrict__ gate_w,
                      const float* __restrict__ gate_b,
                      float* __restrict__ out) {
    __shared__ float As[2][BM][KSTRIDE];
    __shared__ float Bs[2][BN][KSTRIDE];

    const int tid  = threadIdx.x;
    const int lane = tid & 31;
    const int warp = tid >> 5;
    const int wm = warp >> 1;       // 0..3 (M)
    const int wn = warp & 1;        // 0..1 (N)
    const int fr = lane >> 2;       // groupID 0..7
    const int fc = lane & 3;        // threadID_in_group 0..3

    const int bm = blockIdx.y * BM;
    const int bn = blockIdx.x * BN;

    const float4* inF4 = (const float4*)input;
    const float4* stF4 = (const float4*)state;
    const float4* wF4  = (const float4*)gate_w;

    float acc[2][8][4];
#pragma unroll
    for (int i = 0; i < 2; i++)
#pragma unroll
        for (int j = 0; j < 8; j++)
#pragma unroll
            for (int k = 0; k < 4; k++) acc[i][j][k] = 0.0f;

    const int NIT = (IN_DIM + H_DIM) / BK;   // 256
    const int lrow = tid >> 2;               // 0..63, +64 for second half
    const int lc4  = tid & 3;

    // Preload tile 0
    {
#pragma unroll
        for (int t = 0; t < 2; t++) {
            int row = lrow + t * 64;
            int g4  = lc4;
            float4 va = (g4 < IN_DIM / 4)
                ? inF4[(bm + row) * (IN_DIM / 4) + g4]
                : stF4[(bm + row) * (H_DIM / 4) + g4 - IN_DIM / 4];
            float4 vb = wF4[(bn + row) * ((IN_DIM + H_DIM) / 4) + g4];
            store_tf32_v4(&As[0][row][lc4 * 4], va);
            store_tf32_v4(&Bs[0][row][lc4 * 4], vb);
        }
    }
    __syncthreads();

    for (int it = 0; it < NIT; ++it) {
        const int cur = it & 1, nxt = cur ^ 1;
        float4 va[2], vb[2];
        const bool pf = (it + 1 < NIT);
        if (pf) {
            int g4b = (it + 1) * 4;
#pragma unroll
            for (int t = 0; t < 2; t++) {
                int row = lrow + t * 64;
                int g4  = g4b + lc4;
                va[t] = (g4 < IN_DIM / 4)
                    ? inF4[(bm + row) * (IN_DIM / 4) + g4]
                    : stF4[(bm + row) * (H_DIM / 4) + g4 - IN_DIM / 4];
                vb[t] = wF4[(bn + row) * ((IN_DIM + H_DIM) / 4) + g4];
            }
        }
#pragma unroll
        for (int kk = 0; kk < BK; kk += 8) {
            uint32_t a[2][4];
#pragma unroll
            for (int mi = 0; mi < 2; mi++) {
                int r = wm * 32 + mi * 16 + fr;
                a[mi][0] = __float_as_uint(As[cur][r][kk + fc]);
                a[mi][1] = __float_as_uint(As[cur][r + 8][kk + fc]);
                a[mi][2] = __float_as_uint(As[cur][r][kk + fc + 4]);
                a[mi][3] = __float_as_uint(As[cur][r + 8][kk + fc + 4]);
            }
#pragma unroll
            for (int ni = 0; ni < 8; ni++) {
                int n = wn * 64 + ni * 8 + fr;
                uint32_t b0 = __float_as_uint(Bs[cur][n][kk + fc]);
                uint32_t b1 = __float_as_uint(Bs[cur][n][kk + fc + 4]);
                mma_tf32(acc[0][ni], a[0], b0, b1);
                mma_tf32(acc[1][ni], a[1], b0, b1);
            }
        }
        if (pf) {
#pragma unroll
            for (int t = 0; t < 2; t++) {
                int row = lrow + t * 64;
                store_tf32_v4(&As[nxt][row][lc4 * 4], va[t]);
                store_tf32_v4(&Bs[nxt][row][lc4 * 4], vb[t]);
            }
        }
        __syncthreads();
    }

    // Epilogue: bias add + hardtanh(0,1)
    float* out_pg = out + OFF_PREGATE;
    float* out_g  = out + OFF_GATE;
#pragma unroll
    for (int mi = 0; mi < 2; mi++) {
#pragma unroll
        for (int ni = 0; ni < 8; ni++) {
            int r = bm + wm * 32 + mi * 16 + fr;
            int c = bn + wn * 64 + ni * 8 + fc * 2;
            float b0 = gate_b[c], b1 = gate_b[c + 1];
            float pg0 = acc[mi][ni][0] + b0;
            float pg1 = acc[mi][ni][1] + b1;
            float pg2 = acc[mi][ni][2] + b0;
            float pg3 = acc[mi][ni][3] + b1;
            *(float2*)&out_pg[(size_t)r * H_DIM + c]       = make_float2(pg0, pg1);
            *(float2*)&out_pg[(size_t)(r + 8) * H_DIM + c] = make_float2(pg2, pg3);
            *(float2*)&out_g[(size_t)r * H_DIM + c]        = make_float2(clip01(pg0), clip01(pg1));
            *(float2*)&out_g[(size_t)(r + 8) * H_DIM + c]  = make_float2(clip01(pg2), clip01(pg3));
        }
    }
}

// ---------------------------------------------------------------------------
// Kernel 3: values = tanh(input @ w_i^T); pre_h = state*(1-g)+values*g;
//           new_h = relu(pre_h).  Reads gate region written by kernel 2.
// ---------------------------------------------------------------------------
__global__ __launch_bounds__(256, 2)
void gemm_values_kernel(const float* __restrict__ input,
                        const float* __restrict__ state,
                        const float* __restrict__ w_i,
                        float* __restrict__ out) {
    __shared__ float As[2][BM][KSTRIDE];
    __shared__ float Bs[2][BN][KSTRIDE];

    const int tid  = threadIdx.x;
    const int lane = tid & 31;
    const int warp = tid >> 5;
    const int wm = warp >> 1;
    const int wn = warp & 1;
    const int fr = lane >> 2;
    const int fc = lane & 3;

    const int bm = blockIdx.y * BM;
    const int bn = blockIdx.x * BN;

    const float4* inF4 = (const float4*)input;
    const float4* wF4  = (const float4*)w_i;

    float acc[2][8][4];
#pragma unroll
    for (int i = 0; i < 2; i++)
#pragma unroll
        for (int j = 0; j < 8; j++)
#pragma unroll
            for (int k = 0; k < 4; k++) acc[i][j][k] = 0.0f;

    const int NIT = IN_DIM / BK;   // 128
    const int lrow = tid >> 2;
    const int lc4  = tid & 3;

    {
#pragma unroll
        for (int t = 0; t < 2; t++) {
            int row = lrow + t * 64;
            float4 va = inF4[(bm + row) * (IN_DIM / 4) + lc4];
            float4 vb = wF4[(bn + row) * (IN_DIM / 4) + lc4];
            store_tf32_v4(&As[0][row][lc4 * 4], va);
            store_tf32_v4(&Bs[0][row][lc4 * 4], vb);
        }
    }
    __syncthreads();

    for (int it = 0; it < NIT; ++it) {
        const int cur = it & 1, nxt = cur ^ 1;
        float4 va[2], vb[2];
        const bool pf = (it + 1 < NIT);
        if (pf) {
            int g4b = (it + 1) * 4;
#pragma unroll
            for (int t = 0; t < 2; t++) {
                int row = lrow + t * 64;
                int g4  = g4b + lc4;
                va[t] = inF4[(bm + row) * (IN_DIM / 4) + g4];
                vb[t] = wF4[(bn + row) * (IN_DIM / 4) + g4];
            }
        }
#pragma unroll
        for (int kk = 0; kk < BK; kk += 8) {
            uint32_t a[2][4];
#pragma unroll
            for (int mi = 0; mi < 2; mi++) {
                int r = wm * 32 + mi * 16 + fr;
                a[mi][0] = __float_as_uint(As[cur][r][kk + fc]);
                a[mi][1] = __float_as_uint(As[cur][r + 8][kk + fc]);
                a[mi][2] = __float_as_uint(As[cur][r][kk + fc + 4]);
                a[mi][3] = __float_as_uint(As[cur][r + 8][kk + fc + 4]);
            }
#pragma unroll
            for (int ni = 0; ni < 8; ni++) {
                int n = wn * 64 + ni * 8 + fr;
                uint32_t b0 = __float_as_uint(Bs[cur][n][kk + fc]);
                uint32_t b1 = __float_as_uint(Bs[cur][n][kk + fc + 4]);
                mma_tf32(acc[0][ni], a[0], b0, b1);
                mma_tf32(acc[1][ni], a[1], b0, b1);
            }
        }
        if (pf) {
#pragma unroll
            for (int t = 0; t < 2; t++) {
                int row = lrow + t * 64;
                store_tf32_v4(&As[nxt][row][lc4 * 4], va[t]);
                store_tf32_v4(&Bs[nxt][row][lc4 * 4], vb[t]);
            }
        }
        __syncthreads();
    }

    // Epilogue: tanh, blend with state via gate, relu
    float* out_v  = out + OFF_VALUES;
    float* out_ph = out + OFF_PREH;
    float* out_nh = out + OFF_NEWH;
    const float* gate = out + OFF_GATE;

#pragma unroll
    for (int mi = 0; mi < 2; mi++) {
#pragma unroll
        for (int ni = 0; ni < 8; ni++) {
            int r = bm + wm * 32 + mi * 16 + fr;
            int c = bn + wn * 64 + ni * 8 + fc * 2;
#pragma unroll
            for (int half = 0; half < 2; half++) {
                int rr = r + half * 8;
                size_t o = (size_t)rr * H_DIM + c;
                float v0 = tanhf(acc[mi][ni][half * 2 + 0]);
                float v1 = tanhf(acc[mi][ni][half * 2 + 1]);
                float2 g  = *(const float2*)&gate[o];
                float2 s  = *(const float2*)&state[o];
                float ph0 = s.x * (1.0f - g.x) + v0 * g.x;
                float ph1 = s.y * (1.0f - g.y) + v1 * g.y;
                *(float2*)&out_v[o]  = make_float2(v0, v1);
                *(float2*)&out_ph[o] = make_float2(ph0, ph1);
                *(float2*)&out_nh[o] = make_float2(fmaxf(ph0, 0.0f), fmaxf(ph1, 0.0f));
            }
        }
    }
}

// ---------------------------------------------------------------------------
extern "C" void kernel_launch(void* const* d_in, const int* in_sizes, int n_in,
                              void* d_out, int out_size) {
    const float* input  = (const float*)d_in[0];
    const float* state  = (const float*)d_in[1];
    const float* gate_w = (const float*)d_in[2];
    const float* gate_b = (const float*)d_in[3];
    const float* w_i    = (const float*)d_in[4];
    float* out = (float*)d_out;

    // concat copy: 8192*1024 float4 / 256 threads
    concat_kernel<<<(B_DIM * 1024) / 256, 256>>>(input, state, out);

    dim3 grid(H_DIM / BN, B_DIM / BM);   // (16, 64)
    gemm_gate_kernel<<<grid, 256>>>(input, state, gate_w, gate_b, out);
    gemm_values_kernel<<<grid, 256>>>(input, state, w_i, out);
}

// round 5
// speedup vs baseline: 2.0142x; 2.0142x over previous
#include <cuda_runtime.h>
#include <cuda_fp16.h>
#include <stdint.h>
#include <math.h>

// ---------------------------------------------------------------------------
// Problem dims
// ---------------------------------------------------------------------------
#define B_DIM 8192
#define IN_DIM 2048
#define H_DIM 2048
#define CAT_DIM 4096

#define OFF_NEWH    ((size_t)0)
#define OFF_CONCAT  (OFF_NEWH + (size_t)B_DIM * H_DIM)
#define OFF_PREGATE (OFF_CONCAT + (size_t)B_DIM * CAT_DIM)
#define OFF_GATE    (OFF_PREGATE + (size_t)B_DIM * H_DIM)
#define OFF_VALUES  (OFF_GATE + (size_t)B_DIM * H_DIM)
#define OFF_PREH    (OFF_VALUES + (size_t)B_DIM * H_DIM)

// ---------------------------------------------------------------------------
// Static device scratch (no runtime allocation allowed)
// ---------------------------------------------------------------------------
__device__ __half g_a_f16[(size_t)B_DIM * CAT_DIM];   // 64 MB: concat in fp16
__device__ __half g_w_f16[(size_t)H_DIM * CAT_DIM];   // 16 MB: gate_w in fp16
__device__ __half g_wi_f16[(size_t)H_DIM * IN_DIM];   //  8 MB: w_i in fp16

// ---------------------------------------------------------------------------
// Tiling: CTA 128x128, BK=32 (two m16n8k16 steps), 3-stage cp.async pipeline
// smem row: 32 fp16 = 64B data + 16B pad = 80B  -> conflict-free LDS.32 frags
// ---------------------------------------------------------------------------
#define ROWB 80
#define TILE_BYTES (128 * ROWB)          // 10240 per operand
#define STAGE_BYTES (2 * TILE_BYTES)     // 20480
#define NSTAGE 3
#define SMEM_TOTAL (NSTAGE * STAGE_BYTES) // 61440

__device__ __forceinline__ void hmma16816(float* c, const uint32_t* a,
                                          uint32_t b0, uint32_t b1) {
    asm volatile(
        "mma.sync.aligned.m16n8k16.row.col.f32.f16.f16.f32 "
        "{%0,%1,%2,%3},{%4,%5,%6,%7},{%8,%9},{%0,%1,%2,%3};"
        : "+f"(c[0]), "+f"(c[1]), "+f"(c[2]), "+f"(c[3])
        : "r"(a[0]), "r"(a[1]), "r"(a[2]), "r"(a[3]), "r"(b0), "r"(b1));
}

__device__ __forceinline__ float clip01(float x) { return fminf(fmaxf(x, 0.0f), 1.0f); }

__device__ __forceinline__ float fast_tanh(float x) {
    // pre-tanh values here are ~N(0, 0.013); |x| < 0.15 is the near-certain path.
    if (fabsf(x) < 0.15f) {
        float t = x * x;
        return x * fmaf(t, fmaf(t, 0.13333334f, -0.33333334f), 1.0f);
    }
    return tanhf(x);
}

// ---------------------------------------------------------------------------
// Prep: concat(fp32 output) + fp16 copies of concat / gate_w / w_i
// ---------------------------------------------------------------------------
__global__ void prep_kernel(const float4* __restrict__ input,
                            const float4* __restrict__ state,
                            const float4* __restrict__ gate_w,
                            const float4* __restrict__ w_i,
                            float* __restrict__ out) {
    size_t idx = (size_t)blockIdx.x * 256 + threadIdx.x;
    const size_t R1 = (size_t)B_DIM * CAT_DIM / 4;        // 8388608
    const size_t R2 = R1 + (size_t)H_DIM * CAT_DIM / 4;   // +2097152
    const size_t R3 = R2 + (size_t)H_DIM * IN_DIM / 4;    // +1048576

    if (idx < R1) {
        size_t b = idx >> 10, c4 = idx & 1023;
        float4 v = (c4 < 512) ? input[b * 512 + c4] : state[b * 512 + (c4 - 512)];
        ((float4*)(out + OFF_CONCAT))[idx] = v;
        ((__half2*)g_a_f16)[idx * 2]     = __floats2half2_rn(v.x, v.y);
        ((__half2*)g_a_f16)[idx * 2 + 1] = __floats2half2_rn(v.z, v.w);
    } else if (idx < R2) {
        size_t j = idx - R1;
        float4 v = gate_w[j];
        ((__half2*)g_w_f16)[j * 2]     = __floats2half2_rn(v.x, v.y);
        ((__half2*)g_w_f16)[j * 2 + 1] = __floats2half2_rn(v.z, v.w);
    } else if (idx < R3) {
        size_t j = idx - R2;
        float4 v = w_i[j];
        ((__half2*)g_wi_f16)[j * 2]     = __floats2half2_rn(v.x, v.y);
        ((__half2*)g_wi_f16)[j * 2 + 1] = __floats2half2_rn(v.z, v.w);
    }
}

// ---------------------------------------------------------------------------
// Tile loader: A 128 rows x 64B + B 128 rows x 64B = 1024 x 16B cp.async
// ---------------------------------------------------------------------------
template <int BSTRIDE>
__device__ __forceinline__ void load_tile(char* smem, int stage,
                                          const char* aptr, const char* bptr,
                                          int koffB, int tid) {
    char* sbase = smem + stage * STAGE_BYTES;
#pragma unroll
    for (int j = 0; j < 4; j++) {
        int gid = tid + j * 256;
        const char* src;
        char* dst;
        if (gid < 512) {
            int row = gid >> 2, c = gid & 3;
            dst = sbase + row * ROWB + c * 16;
            src = aptr + (size_t)row * 8192 + koffB + c * 16;
        } else {
            int g = gid - 512;
            int row = g >> 2, c = g & 3;
            dst = sbase + TILE_BYTES + row * ROWB + c * 16;
            src = bptr + (size_t)row * BSTRIDE + koffB + c * 16;
        }
        uint32_t d32;
        asm("{ .reg .u64 t; cvta.to.shared.u64 t, %1; cvt.u32.u64 %0, t; }"
            : "=r"(d32) : "l"(dst));
        asm volatile("cp.async.cg.shared.global [%0], [%1], 16;"
                     :: "r"(d32), "l"(src) : "memory");
    }
    asm volatile("cp.async.commit_group;" ::: "memory");
}

// ---------------------------------------------------------------------------
// fp16 HMMA GEMM.  MODE 0: gate (K=4096), MODE 1: values (K=2048)
// Warp grid 4(m) x 2(n); warp tile 32x64: mi=2, ni=8.
// ---------------------------------------------------------------------------
template <int MODE, int NIT, int BSTRIDE>
__global__ __launch_bounds__(256, 2)
void gemm_f16(const char* __restrict__ aroot,
              const char* __restrict__ broot,
              const float* __restrict__ gate_b,
              const float* __restrict__ state,
              float* __restrict__ out) {
    extern __shared__ __align__(128) char smem[];

    const int tid  = threadIdx.x;
    const int lane = tid & 31;
    const int warp = tid >> 5;
    const int wm = warp >> 1;       // 0..3
    const int wn = warp & 1;        // 0..1
    const int fr = lane >> 2;       // groupID 0..7
    const int fc = lane & 3;        // threadInGroup 0..3

    const int bm = blockIdx.y * 128;
    const int bn = blockIdx.x * 128;

    const char* aptr = aroot + (size_t)bm * 8192;     // fp16 row stride 4096 elems
    const char* bptr = broot + (size_t)bn * BSTRIDE;

    float acc[2][8][4];
#pragma unroll
    for (int i = 0; i < 2; i++)
#pragma unroll
        for (int j = 0; j < 8; j++)
#pragma unroll
            for (int k = 0; k < 4; k++) acc[i][j][k] = 0.0f;

    load_tile<BSTRIDE>(smem, 0, aptr, bptr, 0, tid);
    load_tile<BSTRIDE>(smem, 1, aptr, bptr, 64, tid);

    for (int it = 0; it < NIT; ++it) {
        if (it == NIT - 1) asm volatile("cp.async.wait_group 0;" ::: "memory");
        else               asm volatile("cp.async.wait_group 1;" ::: "memory");
        __syncthreads();

        if (it + 2 < NIT)
            load_tile<BSTRIDE>(smem, (it + 2) % NSTAGE, aptr, bptr, (it + 2) * 64, tid);

        const char* sA = smem + (it % NSTAGE) * STAGE_BYTES;
        const char* sB = sA + TILE_BYTES;

#pragma unroll
        for (int ks = 0; ks < 2; ks++) {
            const int kb = ks * 32;                 // 16 fp16 = 32B per k-step
            uint32_t a[2][4];
#pragma unroll
            for (int mi = 0; mi < 2; mi++) {
                int r = wm * 32 + mi * 16 + fr;
                const char* base = sA + r * ROWB + kb + fc * 4;
                a[mi][0] = *(const uint32_t*)(base);
                a[mi][1] = *(const uint32_t*)(base + 8 * ROWB);
                a[mi][2] = *(const uint32_t*)(base + 16);
                a[mi][3] = *(const uint32_t*)(base + 8 * ROWB + 16);
            }
#pragma unroll
            for (int ni = 0; ni < 8; ni++) {
                int n = wn * 64 + ni * 8 + fr;
                const char* base = sB + n * ROWB + kb + fc * 4;
                uint32_t b0 = *(const uint32_t*)(base);
                uint32_t b1 = *(const uint32_t*)(base + 16);
                hmma16816(acc[0][ni], a[0], b0, b1);
                hmma16816(acc[1][ni], a[1], b0, b1);
            }
        }
    }

    // ---------------- Epilogue ----------------
#pragma unroll
    for (int mi = 0; mi < 2; mi++) {
#pragma unroll
        for (int ni = 0; ni < 8; ni++) {
            int r = bm + wm * 32 + mi * 16 + fr;
            int c = bn + wn * 64 + ni * 8 + fc * 2;
            if (MODE == 0) {
                float* out_pg = out + OFF_PREGATE;
                float* out_g  = out + OFF_GATE;
                float b0 = gate_b[c], b1 = gate_b[c + 1];
                float pg0 = acc[mi][ni][0] + b0;
                float pg1 = acc[mi][ni][1] + b1;
                float pg2 = acc[mi][ni][2] + b0;
                float pg3 = acc[mi][ni][3] + b1;
                *(float2*)&out_pg[(size_t)r * H_DIM + c]       = make_float2(pg0, pg1);
                *(float2*)&out_pg[(size_t)(r + 8) * H_DIM + c] = make_float2(pg2, pg3);
                *(float2*)&out_g[(size_t)r * H_DIM + c]        = make_float2(clip01(pg0), clip01(pg1));
                *(float2*)&out_g[(size_t)(r + 8) * H_DIM + c]  = make_float2(clip01(pg2), clip01(pg3));
            } else {
                const float* gate = out + OFF_GATE;
#pragma unroll
                for (int half = 0; half < 2; half++) {
                    size_t o = (size_t)(r + half * 8) * H_DIM + c;
                    float v0 = fast_tanh(acc[mi][ni][half * 2 + 0]);
                    float v1 = fast_tanh(acc[mi][ni][half * 2 + 1]);
                    float2 g = *(const float2*)&gate[o];
                    float2 s = *(const float2*)&state[o];
                    float ph0 = s.x * (1.0f - g.x) + v0 * g.x;
                    float ph1 = s.y * (1.0f - g.y) + v1 * g.y;
                    *(float2*)&out[OFF_VALUES + o] = make_float2(v0, v1);
                    *(float2*)&out[OFF_PREH + o]   = make_float2(ph0, ph1);
                    *(float2*)&out[OFF_NEWH + o]   = make_float2(fmaxf(ph0, 0.0f), fmaxf(ph1, 0.0f));
                }
            }
        }
    }
}

// ---------------------------------------------------------------------------
extern "C" void kernel_launch(void* const* d_in, const int* in_sizes, int n_in,
                              void* d_out, int out_size) {
    const float* input  = (const float*)d_in[0];
    const float* state  = (const float*)d_in[1];
    const float* gate_w = (const float*)d_in[2];
    const float* gate_b = (const float*)d_in[3];
    const float* w_i    = (const float*)d_in[4];
    float* out = (float*)d_out;

    cudaFuncSetAttribute(gemm_f16<0, 128, 8192>,
                         cudaFuncAttributeMaxDynamicSharedMemorySize, SMEM_TOTAL);
    cudaFuncSetAttribute(gemm_f16<1, 64, 4096>,
                         cudaFuncAttributeMaxDynamicSharedMemorySize, SMEM_TOTAL);

    char* a16 = nullptr;
    char* w16 = nullptr;
    char* wi16 = nullptr;
    cudaGetSymbolAddress((void**)&a16, g_a_f16);
    cudaGetSymbolAddress((void**)&w16, g_w_f16);
    cudaGetSymbolAddress((void**)&wi16, g_wi_f16);

    prep_kernel<<<45056, 256>>>((const float4*)input, (const float4*)state,
                                (const float4*)gate_w, (const float4*)w_i, out);

    dim3 grid(H_DIM / 128, B_DIM / 128);   // (16, 64); x = N fastest
    gemm_f16<0, 128, 8192><<<grid, 256, SMEM_TOTAL>>>(a16, w16, gate_b, state, out);
    gemm_f16<1, 64, 4096><<<grid, 256, SMEM_TOTAL>>>(a16, wi16, gate_b, state, out);
}

// round 7
// speedup vs baseline: 2.4312x; 1.2070x over previous
#include <cuda_runtime.h>
#include <cuda_fp16.h>
#include <stdint.h>
#include <math.h>

// ---------------------------------------------------------------------------
// Problem dims
// ---------------------------------------------------------------------------
#define B_DIM 8192
#define IN_DIM 2048
#define H_DIM 2048
#define CAT_DIM 4096

#define OFF_NEWH    ((size_t)0)
#define OFF_CONCAT  (OFF_NEWH + (size_t)B_DIM * H_DIM)
#define OFF_PREGATE (OFF_CONCAT + (size_t)B_DIM * CAT_DIM)
#define OFF_GATE    (OFF_PREGATE + (size_t)B_DIM * H_DIM)
#define OFF_VALUES  (OFF_GATE + (size_t)B_DIM * H_DIM)
#define OFF_PREH    (OFF_VALUES + (size_t)B_DIM * H_DIM)

// ---------------------------------------------------------------------------
// Static device scratch
// ---------------------------------------------------------------------------
__device__ __half g_a_f16[(size_t)B_DIM * CAT_DIM];   // 64 MB concat fp16
__device__ __half g_w_f16[(size_t)H_DIM * CAT_DIM];   // 16 MB gate_w fp16
__device__ __half g_wi_f16[(size_t)H_DIM * IN_DIM];   //  8 MB w_i fp16
__device__ unsigned int g_unit_ctr;                   // persistent work queue
__device__ int g_gate_flag[1024];                     // per-tile gate-done flags

// ---------------------------------------------------------------------------
// Tiling: CTA tile 128x128, BK=32 (two m16n8k16 k-steps), 3-stage cp.async.
// smem row = 64B data + 16B pad = 80B (5 coprime 8 -> ldmatrix conflict-free)
// ---------------------------------------------------------------------------
#define ROWB 80
#define TILE_BYTES (128 * ROWB)            // 10240 per operand
#define STAGE_BYTES (2 * TILE_BYTES)       // 20480
#define NSTAGE 3
#define SMEM_TOTAL (NSTAGE * STAGE_BYTES)  // 61440
#define NTILES 1024                        // 64 bm x 16 bn
#define NUNITS 2048                        // gate tiles then values tiles

__device__ __forceinline__ void hmma16816(float* c, const uint32_t* a,
                                          uint32_t b0, uint32_t b1) {
    asm volatile(
        "mma.sync.aligned.m16n8k16.row.col.f32.f16.f16.f32 "
        "{%0,%1,%2,%3},{%4,%5,%6,%7},{%8,%9},{%0,%1,%2,%3};"
        : "+f"(c[0]), "+f"(c[1]), "+f"(c[2]), "+f"(c[3])
        : "r"(a[0]), "r"(a[1]), "r"(a[2]), "r"(a[3]), "r"(b0), "r"(b1));
}

__device__ __forceinline__ void ldsm_x4(uint32_t* r, uint32_t addr) {
    asm volatile("ldmatrix.sync.aligned.m8n8.x4.shared.b16 {%0,%1,%2,%3}, [%4];"
                 : "=r"(r[0]), "=r"(r[1]), "=r"(r[2]), "=r"(r[3]) : "r"(addr));
}

__device__ __forceinline__ uint32_t smem_u32(const void* p) {
    uint32_t a;
    asm("{ .reg .u64 t; cvta.to.shared.u64 t, %1; cvt.u32.u64 %0, t; }"
        : "=r"(a) : "l"(p));
    return a;
}

__device__ __forceinline__ float clip01(float x) { return fminf(fmaxf(x, 0.0f), 1.0f); }

__device__ __forceinline__ float fast_tanh(float x) {
    if (fabsf(x) < 0.15f) {
        float t = x * x;
        return x * fmaf(t, fmaf(t, 0.13333334f, -0.33333334f), 1.0f);
    }
    return tanhf(x);
}

// ---------------------------------------------------------------------------
// Prep: concat(fp32 out) + fp16 copies + queue/flag reset
// ---------------------------------------------------------------------------
__global__ void prep_kernel(const float4* __restrict__ input,
                            const float4* __restrict__ state,
                            const float4* __restrict__ gate_w,
                            const float4* __restrict__ w_i,
                            float* __restrict__ out) {
    size_t idx = (size_t)blockIdx.x * 256 + threadIdx.x;
    const size_t R1 = (size_t)B_DIM * CAT_DIM / 4;
    const size_t R2 = R1 + (size_t)H_DIM * CAT_DIM / 4;
    const size_t R3 = R2 + (size_t)H_DIM * IN_DIM / 4;

    if (blockIdx.x == 0) {
        if (threadIdx.x == 0) g_unit_ctr = 0;
        for (int i = threadIdx.x; i < NTILES; i += 256) g_gate_flag[i] = 0;
    }

    if (idx < R1) {
        size_t b = idx >> 10, c4 = idx & 1023;
        float4 v = (c4 < 512) ? input[b * 512 + c4] : state[b * 512 + (c4 - 512)];
        ((float4*)(out + OFF_CONCAT))[idx] = v;
        ((__half2*)g_a_f16)[idx * 2]     = __floats2half2_rn(v.x, v.y);
        ((__half2*)g_a_f16)[idx * 2 + 1] = __floats2half2_rn(v.z, v.w);
    } else if (idx < R2) {
        size_t j = idx - R1;
        float4 v = gate_w[j];
        ((__half2*)g_w_f16)[j * 2]     = __floats2half2_rn(v.x, v.y);
        ((__half2*)g_w_f16)[j * 2 + 1] = __floats2half2_rn(v.z, v.w);
    } else if (idx < R3) {
        size_t j = idx - R2;
        float4 v = w_i[j];
        ((__half2*)g_wi_f16)[j * 2]     = __floats2half2_rn(v.x, v.y);
        ((__half2*)g_wi_f16)[j * 2 + 1] = __floats2half2_rn(v.z, v.w);
    }
}

// ---------------------------------------------------------------------------
// Tile loader (runtime B stride): 1024 x 16B cp.async per stage
// ---------------------------------------------------------------------------
__device__ __forceinline__ void load_tile(uint32_t sbase, const char* aptr,
                                          const char* bptr, size_t bstride,
                                          int koff, int tid) {
#pragma unroll
    for (int j = 0; j < 4; j++) {
        int gid = tid + j * 256;
        uint32_t dst;
        const char* src;
        if (gid < 512) {
            int row = gid >> 2, c = gid & 3;
            dst = sbase + row * ROWB + c * 16;
            src = aptr + (size_t)row * 8192 + koff + c * 16;
        } else {
            int g = gid - 512;
            int row = g >> 2, c = g & 3;
            dst = sbase + TILE_BYTES + row * ROWB + c * 16;
            src = bptr + (size_t)row * bstride + koff + c * 16;
        }
        asm volatile("cp.async.cg.shared.global [%0], [%1], 16;"
                     :: "r"(dst), "l"(src) : "memory");
    }
    asm volatile("cp.async.commit_group;" ::: "memory");
}

// ---------------------------------------------------------------------------
// Persistent merged GEMM. Units 0..1023: gate tiles (K=4096).
// Units 1024..2047: values tiles (K=2048), epilogue waits on gate flag.
// Warp grid 4(m) x 2(n), warp tile 32x64: mi=2, ni=8. ldmatrix fragments.
// ---------------------------------------------------------------------------
__global__ __launch_bounds__(256, 2)
void gemm_persist(const float* __restrict__ gate_b,
                  const float* __restrict__ state,
                  float* __restrict__ out) {
    extern __shared__ __align__(128) char smem[];
    __shared__ unsigned s_unit;

    const int tid  = threadIdx.x;
    const int lane = tid & 31;
    const int warp = tid >> 5;
    const int wm = warp >> 1;
    const int wn = warp & 1;
    const int fr = lane >> 2;
    const int fc = lane & 3;

    const uint32_t smem32 = smem_u32(smem);

    // Per-thread ldmatrix offsets (stage-relative)
    uint32_t A_off[2], B_off[4];
#pragma unroll
    for (int mi = 0; mi < 2; mi++)
        A_off[mi] = (wm * 32 + mi * 16 + (lane & 15)) * ROWB + ((lane >> 4) * 16);
#pragma unroll
    for (int q = 0; q < 4; q++)
        B_off[q] = TILE_BYTES +
                   (wn * 64 + q * 16 + (lane & 7) + ((lane >> 4) << 3)) * ROWB +
                   (((lane >> 3) & 1) * 16);

    const char* const a_root  = (const char*)g_a_f16;
    const char* const w_root  = (const char*)g_w_f16;
    const char* const wi_root = (const char*)g_wi_f16;

    for (;;) {
        __syncthreads();                       // smem reuse + s_unit protection
        if (tid == 0) s_unit = atomicAdd(&g_unit_ctr, 1u);
        __syncthreads();
        const unsigned u = s_unit;
        if (u >= NUNITS) break;

        const int mode = (u >= NTILES);        // 0: gate, 1: values
        const int t = u & (NTILES - 1);
        const int bm = (t >> 4) * 128;
        const int bn = (t & 15) * 128;

        const char* aptr = a_root + (size_t)bm * 8192;
        const char* bptr;
        size_t bstride;
        int nit;
        if (!mode) { bptr = w_root  + (size_t)bn * 8192; bstride = 8192; nit = 128; }
        else       { bptr = wi_root + (size_t)bn * 4096; bstride = 4096; nit = 64;  }

        float acc[2][8][4];
#pragma unroll
        for (int i = 0; i < 2; i++)
#pragma unroll
            for (int j = 0; j < 8; j++)
#pragma unroll
                for (int k = 0; k < 4; k++) acc[i][j][k] = 0.0f;

        load_tile(smem32, aptr, bptr, bstride, 0, tid);
        load_tile(smem32 + STAGE_BYTES, aptr, bptr, bstride, 64, tid);

        int stage = 0;
        for (int it = 0; it < nit; ++it) {
            if (it == nit - 1) asm volatile("cp.async.wait_group 0;" ::: "memory");
            else               asm volatile("cp.async.wait_group 1;" ::: "memory");
            __syncthreads();

            if (it + 2 < nit) {
                int ns = stage + 2;
                if (ns >= NSTAGE) ns -= NSTAGE;
                load_tile(smem32 + ns * STAGE_BYTES, aptr, bptr, bstride,
                          (it + 2) * 64, tid);
            }

            const uint32_t sbase = smem32 + stage * STAGE_BYTES;
#pragma unroll
            for (int ks = 0; ks < 2; ks++) {
                const uint32_t kb = ks * 32;
                uint32_t a[2][4], b[4][4];
                ldsm_x4(a[0], sbase + A_off[0] + kb);
                ldsm_x4(a[1], sbase + A_off[1] + kb);
#pragma unroll
                for (int q = 0; q < 4; q++) ldsm_x4(b[q], sbase + B_off[q] + kb);
#pragma unroll
                for (int ni = 0; ni < 8; ni++) {
                    uint32_t b0 = b[ni >> 1][(ni & 1) * 2];
                    uint32_t b1 = b[ni >> 1][(ni & 1) * 2 + 1];
                    hmma16816(acc[0][ni], a[0], b0, b1);
                    hmma16816(acc[1][ni], a[1], b0, b1);
                }
            }
            if (++stage == NSTAGE) stage = 0;
        }

        // ---------------- Epilogue ----------------
        if (!mode) {
            float* out_pg = out + OFF_PREGATE;
            float* out_g  = out + OFF_GATE;
#pragma unroll
            for (int mi = 0; mi < 2; mi++) {
#pragma unroll
                for (int ni = 0; ni < 8; ni++) {
                    int r = bm + wm * 32 + mi * 16 + fr;
                    int c = bn + wn * 64 + ni * 8 + fc * 2;
                    float b0 = gate_b[c], b1 = gate_b[c + 1];
                    float pg0 = acc[mi][ni][0] + b0;
                    float pg1 = acc[mi][ni][1] + b1;
                    float pg2 = acc[mi][ni][2] + b0;
                    float pg3 = acc[mi][ni][3] + b1;
                    *(float2*)&out_pg[(size_t)r * H_DIM + c]       = make_float2(pg0, pg1);
                    *(float2*)&out_pg[(size_t)(r + 8) * H_DIM + c] = make_float2(pg2, pg3);
                    *(float2*)&out_g[(size_t)r * H_DIM + c]        = make_float2(clip01(pg0), clip01(pg1));
                    *(float2*)&out_g[(size_t)(r + 8) * H_DIM + c]  = make_float2(clip01(pg2), clip01(pg3));
                }
            }
            __threadfence();
            __syncthreads();
            if (tid == 0) atomicExch(&g_gate_flag[t], 1);
        } else {
            if (tid == 0) {
                while (atomicAdd(&g_gate_flag[t], 0) == 0) { __nanosleep(64); }
                __threadfence();
            }
            __syncthreads();
            const float* gate = out + OFF_GATE;
#pragma unroll
            for (int mi = 0; mi < 2; mi++) {
#pragma unroll
                for (int ni = 0; ni < 8; ni++) {
                    int r = bm + wm * 32 + mi * 16 + fr;
                    int c = bn + wn * 64 + ni * 8 + fc * 2;
#pragma unroll
                    for (int half = 0; half < 2; half++) {
                        size_t o = (size_t)(r + half * 8) * H_DIM + c;
                        float v0 = fast_tanh(acc[mi][ni][half * 2 + 0]);
                        float v1 = fast_tanh(acc[mi][ni][half * 2 + 1]);
                        float2 g = *(const float2*)&gate[o];
                        float2 s = *(const float2*)&state[o];
                        float ph0 = s.x * (1.0f - g.x) + v0 * g.x;
                        float ph1 = s.y * (1.0f - g.y) + v1 * g.y;
                        *(float2*)&out[OFF_VALUES + o] = make_float2(v0, v1);
                        *(float2*)&out[OFF_PREH + o]   = make_float2(ph0, ph1);
                        *(float2*)&out[OFF_NEWH + o]   = make_float2(fmaxf(ph0, 0.0f),
                                                                    fmaxf(ph1, 0.0f));
                    }
                }
            }
        }
    }
}

// ---------------------------------------------------------------------------
extern "C" void kernel_launch(void* const* d_in, const int* in_sizes, int n_in,
                              void* d_out, int out_size) {
    const float* input  = (const float*)d_in[0];
    const float* state  = (const float*)d_in[1];
    const float* gate_w = (const float*)d_in[2];
    const float* gate_b = (const float*)d_in[3];
    const float* w_i    = (const float*)d_in[4];
    float* out = (float*)d_out;

    cudaFuncSetAttribute(gemm_persist,
                         cudaFuncAttributeMaxDynamicSharedMemorySize, SMEM_TOTAL);

    prep_kernel<<<45056, 256>>>((const float4*)input, (const float4*)state,
                                (const float4*)gate_w, (const float4*)w_i, out);

    gemm_persist<<<296, 256, SMEM_TOTAL>>>(gate_b, state, out);
}